// round 5
// baseline (speedup 1.0000x reference)
#include <cuda_runtime.h>
#include <cstdint>

#define NPTS 16384
#define NDIM 64
#define NB   8
#define NSEG (NB * NDIM)
#define EPSF 0.1f
#define MINS 5
#define NCMAX 512
#define FULLM 0xffffffffu
#define NSM 148

// ---------------- global scratch (no allocations allowed) ----------------
__device__ float    g_xt[(size_t)NB * NDIM * NPTS];   // transposed features (B,D,N)
__device__ short    g_lab[(size_t)NB * NDIM * NPTS];  // per-dim local labels (-1 noise)
__device__ int      g_ncl[NSEG];                      // clusters per (b,d)
__device__ int      g_off[NSEG];                      // exclusive prefix per batch
__device__ unsigned g_ctr;                            // work-steal counter

extern __shared__ unsigned char dsm[];

// ---------------- kernel 0: transpose (B,N,D) -> (B,D,N)  (+ counter reset) ----------------
__global__ void transpose_kernel(const float* __restrict__ f) {
    __shared__ float tile[64][65];
    if (blockIdx.x == 0 && threadIdx.x == 0) g_ctr = 0u;   // reset work counter each launch
    int b  = blockIdx.x >> 8;          // 8 batches
    int n0 = (blockIdx.x & 255) << 6;  // 256 tiles of 64 rows
    int tid = threadIdx.x;
    const float* src = f + ((size_t)b * NPTS + n0) * NDIM;
    #pragma unroll
    for (int idx = tid; idx < 64 * 64; idx += 256) {
        int n = idx >> 6, d = idx & 63;
        tile[n][d] = src[idx];
    }
    __syncthreads();
    #pragma unroll
    for (int idx = tid; idx < 64 * 64; idx += 256) {
        int d = idx >> 6, n = idx & 63;
        g_xt[(((size_t)b * NDIM + d) << 14) + n0 + n] = tile[n][d];
    }
}

// ---------------- block scan helpers (1024 threads = 32 warps) ----------------
__device__ __forceinline__ int blkscan_excl_add(int v, int* aux) {
    int lane = threadIdx.x & 31, wid = threadIdx.x >> 5;
    int incl = v;
    #pragma unroll
    for (int o = 1; o < 32; o <<= 1) {
        int u = __shfl_up_sync(FULLM, incl, o);
        if (lane >= o) incl += u;
    }
    if (lane == 31) aux[wid] = incl;
    __syncthreads();
    if (wid == 0) {
        int w = aux[lane];
        #pragma unroll
        for (int o = 1; o < 32; o <<= 1) {
            int u = __shfl_up_sync(FULLM, w, o);
            if (lane >= o) w += u;
        }
        aux[lane] = w;
    }
    __syncthreads();
    int wex = __shfl_up_sync(FULLM, incl, 1);
    if (lane == 0) wex = 0;
    int pre = (wid > 0) ? (wex + aux[wid - 1]) : wex;
    __syncthreads();
    return pre;
}

__device__ __forceinline__ int blkscan_excl_max(int v, int* aux) {
    int lane = threadIdx.x & 31, wid = threadIdx.x >> 5;
    int incl = v;
    #pragma unroll
    for (int o = 1; o < 32; o <<= 1) {
        int u = __shfl_up_sync(FULLM, incl, o);
        if (lane >= o) incl = max(incl, u);
    }
    if (lane == 31) aux[wid] = incl;
    __syncthreads();
    if (wid == 0) {
        int w = aux[lane];
        #pragma unroll
        for (int o = 1; o < 32; o <<= 1) {
            int u = __shfl_up_sync(FULLM, w, o);
            if (lane >= o) w = max(w, u);
        }
        aux[lane] = w;
    }
    __syncthreads();
    int wex = __shfl_up_sync(FULLM, incl, 1);
    if (lane == 0) wex = -1;
    int pre = (wid > 0) ? max(wex, aux[wid - 1]) : wex;
    __syncthreads();
    return pre;
}

// suffix (reverse) exclusive min over HIGHER tids
__device__ __forceinline__ int blkscan_excl_min_suffix(int v, int* aux) {
    int lane = threadIdx.x & 31, wid = threadIdx.x >> 5;
    int incl = v;
    #pragma unroll
    for (int o = 1; o < 32; o <<= 1) {
        int u = __shfl_down_sync(FULLM, incl, o);
        if (lane < 32 - o) incl = min(incl, u);
    }
    if (lane == 0) aux[wid] = incl;
    __syncthreads();
    if (wid == 0) {
        int w = aux[lane];
        #pragma unroll
        for (int o = 1; o < 32; o <<= 1) {
            int u = __shfl_down_sync(FULLM, w, o);
            if (lane < 32 - o) w = min(w, u);
        }
        aux[lane] = w;
    }
    __syncthreads();
    int wex = __shfl_down_sync(FULLM, incl, 1);
    if (lane == 31) wex = NPTS;
    int pre = (wid < 31) ? min(wex, aux[wid + 1]) : wex;
    __syncthreads();
    return pre;
}

// ---------------- kernel 1: persistent per-(b,d) 1D DBSCAN ----------------
// dynamic smem layout (bytes):
//   [0,      65536)  u32 k0   -> later float xs[16384]
//   [65536,  98304)  u16 p0   -> ord[16384]
//   [98304, 163840)  u32 k1   -> later s16 lastc @98304, s16 nextc @131072
//   [163840,196608)  u16 p1   -> later s16 cid
//   [196608,229376)  u32 wh[32][256]  -> later u8 core[16384]
//   [229376,230400)  i32 bintot[256]
//   [230400,230528)  i32 aux[32]
//   [230528,230532)  i32 s_bd
#define SMEM_BYTES 230532

__global__ void __launch_bounds__(1024, 1) dbscan_kernel() {
    uint32_t*       k0    = (uint32_t*)dsm;
    uint16_t*       p0    = (uint16_t*)(dsm + 65536);
    uint32_t*       k1    = (uint32_t*)(dsm + 98304);
    uint16_t*       p1    = (uint16_t*)(dsm + 163840);
    uint32_t*       wh    = (uint32_t*)(dsm + 196608);
    int*            bintot= (int*)(dsm + 229376);
    int*            aux   = (int*)(dsm + 230400);
    int*            s_bd  = (int*)(dsm + 230528);

    float*          xs    = (float*)dsm;
    uint16_t*       ordv  = p0;
    short*          lastc = (short*)(dsm + 98304);
    short*          nextc = (short*)(dsm + 131072);
    short*          cidv  = (short*)(dsm + 163840);
    unsigned char*  corev = (unsigned char*)(dsm + 196608);

    int tid  = threadIdx.x;
    int lane = tid & 31;
    int wid  = tid >> 5;
    unsigned mask_lt = (1u << lane) - 1u;
    int ibase = (wid << 9) + lane;
    int base  = tid << 4;

    for (;;) {
        if (tid == 0) *s_bd = (int)atomicAdd(&g_ctr, 1u);
        __syncthreads();
        int bd = *s_bd;
        if (bd >= NSEG) return;
        const float* x = g_xt + ((size_t)bd << 14);

        // phase 0: order-preserving float->uint keys, payload = index
        #pragma unroll 4
        for (int q = 0; q < 16; q++) {
            int i = ibase + (q << 5);
            unsigned u = __float_as_uint(x[i]);
            unsigned s = (u & 0x80000000u) ? ~u : (u | 0x80000000u);
            k0[i] = s;
            p0[i] = (uint16_t)i;
        }
        __syncthreads();

        // phase 1: 4-pass 8-bit LSD radix sort (warp-major layout => stable)
        uint32_t* kcur = k0; uint16_t* pcur = p0;
        uint32_t* kalt = k1; uint16_t* palt = p1;
        for (int pass = 0; pass < 4; pass++) {
            int shift = pass << 3;
            // zero per-warp histograms (32KB)
            #pragma unroll 2
            for (int j = tid; j < 32 * 256; j += 1024) wh[j] = 0;
            __syncthreads();
            // histogram: warp-private rows, leader plain RMW
            #pragma unroll 4
            for (int q = 0; q < 16; q++) {
                unsigned d = (kcur[ibase + (q << 5)] >> shift) & 255u;
                unsigned m = __match_any_sync(FULLM, d);
                if ((m & mask_lt) == 0) wh[(wid << 8) + d] += __popc(m);
                __syncwarp();
            }
            __syncthreads();
            // bin totals + exclusive scan over 256 bins
            int v = 0;
            if (tid < 256) {
                int s = 0;
                #pragma unroll 4
                for (int w2 = 0; w2 < 32; w2++) s += (int)wh[(w2 << 8) + tid];
                v = s;
            }
            int incl = v;
            #pragma unroll
            for (int o = 1; o < 32; o <<= 1) {
                int u = __shfl_up_sync(FULLM, incl, o);
                if (lane >= o) incl += u;
            }
            if (tid < 256 && lane == 31) aux[wid] = incl;
            __syncthreads();
            if (tid == 0) {
                int r = 0;
                #pragma unroll
                for (int w2 = 0; w2 < 8; w2++) { int c = aux[w2]; aux[w2] = r; r += c; }
            }
            __syncthreads();
            if (tid < 256) bintot[tid] = incl - v + aux[wid];
            __syncthreads();
            // per-(warp,bin) bases, warp-major within bin
            if (tid < 256) {
                int run = bintot[tid];
                #pragma unroll 4
                for (int w2 = 0; w2 < 32; w2++) {
                    int c = (int)wh[(w2 << 8) + tid];
                    wh[(w2 << 8) + tid] = (uint32_t)run;
                    run += c;
                }
            }
            __syncthreads();
            // stable rank & scatter
            #pragma unroll 2
            for (int q = 0; q < 16; q++) {
                int i = ibase + (q << 5);
                unsigned k = kcur[i];
                uint16_t pl = pcur[i];
                unsigned d = (k >> shift) & 255u;
                unsigned m = __match_any_sync(FULLM, d);
                int leader = __ffs(m) - 1;
                int myoff = __popc(m & mask_lt);
                int base2 = 0;
                if (myoff == 0) {
                    int a = (wid << 8) + d;
                    base2 = (int)wh[a];
                    wh[a] = (uint32_t)(base2 + __popc(m));
                }
                base2 = __shfl_sync(FULLM, base2, leader);
                int dst = base2 + myoff;
                kalt[dst] = k;
                palt[dst] = pl;
                __syncwarp();
            }
            __syncthreads();
            uint32_t* tk = kcur; kcur = kalt; kalt = tk;
            uint16_t* tp = pcur; pcur = palt; palt = tp;
        }
        // after 4 passes sorted data is back in k0/p0

        // phase 2: keys -> float values in place
        #pragma unroll 4
        for (int i = tid; i < NPTS; i += 1024) {
            unsigned s = k0[i];
            unsigned u = (s & 0x80000000u) ? (s & 0x7fffffffu) : ~s;
            ((uint32_t*)xs)[i] = u;
        }
        __syncthreads();

        // phase 3: core test — 2 binary searches per THREAD + monotone advance
        {
            float v0 = xs[base];
            float tU = v0 + EPSF, tL = v0 - EPSF;
            int lo = 0, hi = NPTS;
            while (lo < hi) { int m = (lo + hi) >> 1; if (xs[m] <= tU) lo = m + 1; else hi = m; }
            int phi = lo;
            lo = 0; hi = NPTS;
            while (lo < hi) { int m = (lo + hi) >> 1; if (xs[m] < tL) lo = m + 1; else hi = m; }
            int plo = lo;
            corev[base] = (unsigned char)((phi - plo) >= MINS);
            #pragma unroll 1
            for (int q = 1; q < 16; q++) {
                float v = xs[base + q];
                float u2 = v + EPSF, l2 = v - EPSF;
                while (phi < NPTS && xs[phi] <= u2) phi++;
                while (plo < NPTS && xs[plo] <  l2) plo++;
                corev[base + q] = (unsigned char)((phi - plo) >= MINS);
            }
        }
        __syncthreads();

        // phase 4: forward inclusive max of (core ? i : -1) -> nearest left core
        {
            int run = -1;
            #pragma unroll 4
            for (int q = 0; q < 16; q++) {
                int i = base + q;
                int v = corev[i] ? i : -1;
                if (v > run) run = v;
                lastc[i] = (short)run;
            }
            int pre = blkscan_excl_max(run, aux);
            #pragma unroll 4
            for (int q = 0; q < 16; q++) {
                int i = base + q;
                int c = (int)lastc[i];
                if (pre > c) lastc[i] = (short)pre;
            }
        }
        __syncthreads();

        // phase 5: new_cluster + cumsum -> cid (chunk-local through smem, no reg array)
        {
            int run = 0;
            #pragma unroll 4
            for (int q = 0; q < 16; q++) {
                int i = base + q;
                int p = (i == 0) ? -1 : (int)lastc[i - 1];
                float pv = (p >= 0) ? xs[p] : -INFINITY;
                int nc = (corev[i] && ((xs[i] - pv) > EPSF)) ? 1 : 0;
                run += nc;
                cidv[i] = (short)run;                 // chunk-local inclusive
            }
            int pre = blkscan_excl_add(run, aux);
            #pragma unroll 4
            for (int q = 0; q < 16; q++) {
                int i = base + q;
                cidv[i] = (short)((int)cidv[i] + pre - 1);
            }
        }
        __syncthreads();

        // phase 6: backward inclusive min of (core ? i : NPTS) -> nearest right core
        {
            int run = NPTS;
            #pragma unroll 4
            for (int q = 15; q >= 0; q--) {
                int i = base + q;
                int v = corev[i] ? i : NPTS;
                if (v < run) run = v;
                nextc[i] = (short)run;                // chunk-local suffix inclusive
            }
            int pre = blkscan_excl_min_suffix(run, aux);
            #pragma unroll 4
            for (int q = 0; q < 16; q++) {
                int i = base + q;
                int v = (int)nextc[i];
                if (pre < v) nextc[i] = (short)pre;
            }
        }
        __syncthreads();

        // phase 7: labels -> unsort to g_lab; write ncl
        #pragma unroll 2
        for (int q = 0; q < 16; q++) {
            int i = base + q;
            int lab;
            if (corev[i]) {
                lab = (int)cidv[i];
            } else {
                int lc = (int)lastc[i], rc = (int)nextc[i];
                float lv = (lc >= 0)   ? xs[lc] : -INFINITY;
                float rv = (rc < NPTS) ? xs[rc] :  INFINITY;
                float dl = xs[i] - lv;
                float dr = rv - xs[i];
                float mn = dl < dr ? dl : dr;
                if (mn <= EPSF) lab = (dl <= dr) ? (int)cidv[lc] : (int)cidv[rc];
                else            lab = -1;
            }
            g_lab[((size_t)bd << 14) + ordv[i]] = (short)lab;
            if (i == NPTS - 1) g_ncl[bd] = (int)cidv[i] + 1;
        }
        __syncthreads();   // protect smem before next work item overwrites
    }
}

// ---------------- kernel 2: per-batch exclusive prefix of ncl over dims ----------------
__global__ void offsets_kernel() {
    __shared__ int s[NSEG];
    int t = threadIdx.x;
    s[t] = g_ncl[t];
    __syncthreads();
    int b = t >> 6, d = t & 63;
    int off = 0;
    for (int j = 0; j < d; j++) off += s[(b << 6) + j];
    g_off[t] = off;
}

// ---------------- kernel 3: fused zero + scatter ----------------
__global__ void scatter_kernel(float* __restrict__ out) {
    __shared__ short labs[64 * 128];   // [d][n]
    __shared__ int   offs[64];
    int b  = blockIdx.x >> 7;          // 8 batches
    int n0 = (blockIdx.x & 127) << 7;  // 128 tiles of 128 rows
    int tid = threadIdx.x;
    if (tid < 64) offs[tid] = g_off[(b << 6) + tid];
    for (int idx = tid; idx < 64 * 128; idx += 256) {
        int d = idx >> 7, n = idx & 127;
        labs[idx] = g_lab[(((size_t)(b * NDIM + d)) << 14) + n0 + n];
    }
    __syncthreads();
    float* o = out + (((size_t)b * NPTS) + n0) * NCMAX;
    float4* o4 = (float4*)o;
    float4 z = make_float4(0.f, 0.f, 0.f, 0.f);
    for (int idx = tid; idx < 128 * NCMAX / 4; idx += 256) o4[idx] = z;
    __syncthreads();
    for (int idx = tid; idx < 128 * 64; idx += 256) {
        int n = idx >> 6, d = idx & 63;
        int lab = (int)labs[d * 128 + n];
        if (lab >= 0) {
            int g = lab + offs[d];
            if (g < NCMAX) o[(size_t)n * NCMAX + g] = 1.0f;
        }
    }
}

// ---------------- entry point ----------------
extern "C" void kernel_launch(void* const* d_in, const int* in_sizes, int n_in,
                              void* d_out, int out_size) {
    (void)in_sizes; (void)n_in; (void)out_size;
    const float* f = (const float*)d_in[0];

    cudaFuncSetAttribute(dbscan_kernel,
                         cudaFuncAttributeMaxDynamicSharedMemorySize, SMEM_BYTES);

    transpose_kernel<<<NB * (NPTS / 64), 256>>>(f);
    dbscan_kernel<<<NSM, 1024, SMEM_BYTES>>>();
    offsets_kernel<<<1, NSEG>>>();
    scatter_kernel<<<NB * (NPTS / 128), 256>>>((float*)d_out);
}